// round 16
// baseline (speedup 1.0000x reference)
#include <cuda_runtime.h>
#include <cuda_bf16.h>
#include <cstdint>
#include <cstddef>

#define kB  2
#define kS  2048
#define kDM 1024
#define kNH 16
#define kDH 64
#define kM  (kB * kS)

// Scratch (static device globals; no allocation allowed)
__device__ __nv_bfloat16 g_Wt[4][kDM * kDM];   // bf16 weights transposed [n][k]
__device__ __nv_bfloat16 g_Ab[3][kM * kDM];    // bf16 copies of q,k,v
__device__ __nv_bfloat16 g_Qh[kM * kDM];       // pre-scaled by ce (Wq folded)
__device__ __nv_bfloat16 g_Kh[kM * kDM];
__device__ __nv_bfloat16 g_Vh[kM * kDM];
__device__ __nv_bfloat16 g_AO[kM * kDM];
__device__ float         g_X [kM * kDM];

// ---------------------------------------------------------------------------
__device__ __forceinline__ uint32_t packbf(float lo, float hi) {
    uint32_t r;
    asm("cvt.rn.bf16x2.f32 %0, %1, %2;" : "=r"(r) : "f"(hi), "f"(lo));
    return r;
}
__device__ __forceinline__ uint32_t ex2bf2(uint32_t x) {
    uint32_t r;
    asm("ex2.approx.ftz.bf16x2 %0, %1;" : "=r"(r) : "r"(x));
    return r;
}
__device__ __forceinline__ void mma16816(float c[4], const uint32_t a[4], uint32_t b0, uint32_t b1) {
    asm volatile(
        "mma.sync.aligned.m16n8k16.row.col.f32.bf16.bf16.f32 "
        "{%0,%1,%2,%3}, {%4,%5,%6,%7}, {%8,%9}, {%0,%1,%2,%3};"
        : "+f"(c[0]), "+f"(c[1]), "+f"(c[2]), "+f"(c[3])
        : "r"(a[0]), "r"(a[1]), "r"(a[2]), "r"(a[3]), "r"(b0), "r"(b1));
}
__device__ __forceinline__ void ldsm4(uint32_t r[4], uint32_t addr) {
    asm volatile("ldmatrix.sync.aligned.m8n8.x4.shared.b16 {%0,%1,%2,%3}, [%4];"
                 : "=r"(r[0]), "=r"(r[1]), "=r"(r[2]), "=r"(r[3]) : "r"(addr));
}
__device__ __forceinline__ void ldsm4t(uint32_t r[4], uint32_t addr) {
    asm volatile("ldmatrix.sync.aligned.m8n8.x4.trans.shared.b16 {%0,%1,%2,%3}, [%4];"
                 : "=r"(r[0]), "=r"(r[1]), "=r"(r[2]), "=r"(r[3]) : "r"(addr));
}
__device__ __forceinline__ void cpasync16(uint32_t dst, const void* src) {
    asm volatile("cp.async.cg.shared.global [%0], [%1], 16;" :: "r"(dst), "l"(src));
}
#define CP_COMMIT()  asm volatile("cp.async.commit_group;" ::: "memory")
#define CP_WAIT0()   asm volatile("cp.async.wait_group 0;" ::: "memory")
#define CP_WAIT1()   asm volatile("cp.async.wait_group 1;" ::: "memory")

// ---------------------------------------------------------------------------
// Fused prep: z<4 -> weight transpose+convert (z==0 folds ce into Wq);
// z in 4..6 -> q,k,v fp32->bf16.
// ---------------------------------------------------------------------------
__global__ void prep_kernel(
    const float* __restrict__ q, const float* __restrict__ k, const float* __restrict__ v,
    const float* __restrict__ Wq, const float* __restrict__ Wk,
    const float* __restrict__ Wv, const float* __restrict__ Wfc)
{
    const int z = blockIdx.z;
    if (z < 4) {
        if (blockIdx.x >= 32 || blockIdx.y >= 32) return;
        __shared__ float tile[32][33];
        const float* W = (z == 0) ? Wq : (z == 1) ? Wk : (z == 2) ? Wv : Wfc;
        const float scale = (z == 0) ? 0.125f * 1.4426950408889634f : 1.0f;
        const int n0 = blockIdx.x * 32, k0 = blockIdx.y * 32;
        const int tx = threadIdx.x, ty = threadIdx.y;
#pragma unroll
        for (int j = 0; j < 4; j++)
            tile[ty + 8 * j][tx] = W[(size_t)(k0 + ty + 8 * j) * kDM + n0 + tx];
        __syncthreads();
#pragma unroll
        for (int j = 0; j < 4; j++)
            g_Wt[z][(size_t)(n0 + ty + 8 * j) * kDM + k0 + tx] =
                __float2bfloat16(tile[tx][ty + 8 * j] * scale);
    } else {
        const float* src = (z == 4) ? q : (z == 5) ? k : v;
        const int bid = blockIdx.y * 64 + blockIdx.x;
        const int tid = threadIdx.y * 32 + threadIdx.x;
        const size_t i = (size_t)bid * 256 + tid;
        float4 x = ((const float4*)src)[i];
        uint2 o;
        o.x = packbf(x.x, x.y);
        o.y = packbf(x.z, x.w);
        ((uint2*)g_Ab[z - 4])[i] = o;
    }
}

// ---------------------------------------------------------------------------
// 128x128 GEMM CTA tile, 128 threads = 4 warps, warp tile 64x64 (2x2 warp
// grid) -> halves LDSM bytes per MMA vs 32x64. 3-stage cp.async, k-chunk 32.
// ---------------------------------------------------------------------------
template <bool OUTF32>
__device__ __forceinline__ void gemm_body(
    const __nv_bfloat16* __restrict__ A, const __nv_bfloat16* __restrict__ Bt,
    void* Cp, const float* __restrict__ bias, const float* __restrict__ resid,
    int m0, int n0)
{
    constexpr int ST = 20;  // 16 data words + 4 pad
    __shared__ uint32_t sA[3][128 * ST];
    __shared__ uint32_t sB[3][128 * ST];

    const int tid = threadIdx.x, lane = tid & 31, wid = tid >> 5;
    const int wm = wid >> 1, wn = wid & 1;   // 2x2 warp grid, 64x64 tiles
    const int tg = lane & 3, gr = lane >> 2;

    const uint32_t aA = (uint32_t)__cvta_generic_to_shared(sA);
    const uint32_t aB = (uint32_t)__cvta_generic_to_shared(sB);

    // cp.async: thread t loads row t of A and row t of B (32 bf16 = 4 chunks)
    const __nv_bfloat16* gA = A + (size_t)(m0 + tid) * kDM;
    const __nv_bfloat16* gB = Bt + (size_t)(n0 + tid) * kDM;
    const uint32_t dA = aA + (tid * ST) * 4;
    const uint32_t dB = aB + (tid * ST) * 4;
    constexpr uint32_t BUFB = 128 * ST * 4;

    auto ISSUE = [&](int kt, int buf) {
        const __nv_bfloat16* pa = gA + kt * 32;
        const __nv_bfloat16* pb = gB + kt * 32;
        const uint32_t bo = buf * BUFB;
#pragma unroll
        for (int j = 0; j < 4; j++) {
            cpasync16(dA + bo + j * 16, pa + j * 8);
            cpasync16(dB + bo + j * 16, pb + j * 8);
        }
    };

    // ldmatrix lane address components
    const int a_sub = ((lane >> 3) & 1) * 8 + (lane & 7);
    const int a_wrd = (lane >> 4) * 4;
    const int b_sub = ((lane >> 4) & 1) * 8 + (lane & 7);
    const int b_wrd = ((lane >> 3) & 1) * 4;

    float acc[4][8][4];
#pragma unroll
    for (int i = 0; i < 4; i++)
#pragma unroll
        for (int j = 0; j < 8; j++)
#pragma unroll
            for (int l = 0; l < 4; l++) acc[i][j][l] = 0.f;

    ISSUE(0, 0); CP_COMMIT();
    ISSUE(1, 1); CP_COMMIT();

    int cur = 0;
    for (int kt = 0; kt < 32; kt++) {
        if (kt == 31) { CP_WAIT0(); } else { CP_WAIT1(); }
        __syncthreads();
        if (kt + 2 < 32) {
            int nx = cur + 2; if (nx >= 3) nx -= 3;
            ISSUE(kt + 2, nx); CP_COMMIT();
        }

        const uint32_t sAb = aA + cur * BUFB;
        const uint32_t sBb = aB + cur * BUFB;
#pragma unroll
        for (int ks = 0; ks < 2; ks++) {
            uint32_t af[4][4];
#pragma unroll
            for (int mf = 0; mf < 4; mf++)
                ldsm4(af[mf], sAb + ((wm * 64 + mf * 16 + a_sub) * ST + ks * 8 + a_wrd) * 4);
#pragma unroll
            for (int p = 0; p < 4; p++) {
                uint32_t bq[4];
                ldsm4(bq, sBb + ((wn * 64 + p * 16 + b_sub) * ST + ks * 8 + b_wrd) * 4);
#pragma unroll
                for (int mf = 0; mf < 4; mf++) {
                    mma16816(acc[mf][2 * p],     af[mf], bq[0], bq[1]);
                    mma16816(acc[mf][2 * p + 1], af[mf], bq[2], bq[3]);
                }
            }
        }
        cur = (cur + 1 == 3) ? 0 : cur + 1;
    }

    if (OUTF32) {
        float* C = (float*)Cp;
#pragma unroll
        for (int mf = 0; mf < 4; mf++)
#pragma unroll
            for (int nf = 0; nf < 8; nf++) {
                const int col = n0 + wn * 64 + nf * 8 + tg * 2;
#pragma unroll
                for (int rr = 0; rr < 2; rr++) {
                    const int r = m0 + wm * 64 + mf * 16 + gr + rr * 8;
                    float2 v;
                    v.x = acc[mf][nf][rr * 2 + 0] + bias[col]     + resid[(size_t)r * kDM + col];
                    v.y = acc[mf][nf][rr * 2 + 1] + bias[col + 1] + resid[(size_t)r * kDM + col + 1];
                    *(float2*)(C + (size_t)r * kDM + col) = v;
                }
            }
    } else {
        uint32_t* C = (uint32_t*)Cp;
        const int colw = (n0 >> 1) + wn * 32;
#pragma unroll
        for (int mf = 0; mf < 4; mf++)
#pragma unroll
            for (int nf = 0; nf < 8; nf++) {
#pragma unroll
                for (int rr = 0; rr < 2; rr++) {
                    const int r = m0 + wm * 64 + mf * 16 + gr + rr * 8;
                    C[(size_t)r * 512 + colw + nf * 4 + tg] =
                        packbf(acc[mf][nf][rr * 2 + 0], acc[mf][nf][rr * 2 + 1]);
                }
            }
    }
}

__global__ __launch_bounds__(128, 2) void gemm_qkv_kernel() {
    const int z = blockIdx.z;
    __nv_bfloat16* C = (z == 0) ? g_Qh : (z == 1) ? g_Kh : g_Vh;
    gemm_body<false>(g_Ab[z], g_Wt[z], C, nullptr, nullptr, blockIdx.y * 128, blockIdx.x * 128);
}

__global__ __launch_bounds__(128, 2) void gemm_out_kernel(
    const float* __restrict__ bfc, const float* __restrict__ resid)
{
    gemm_body<true>(g_AO, g_Wt[3], g_X, bfc, resid, blockIdx.y * 128, blockIdx.x * 128);
}

// ---------------------------------------------------------------------------
// Flash attention (R15 version, unchanged): 128-key K/V tiles double-buffered
// (two 64-key halves per barrier), Q pre-scaled via Wq fold, packed bf16x2
// exp, row sums via ones-column MMA, V via ldmatrix.trans.
// ---------------------------------------------------------------------------
__global__ __launch_bounds__(256, 2) void attn_kernel() {
    constexpr int ST = 36;
    __shared__ uint32_t sm[18432];  // [K0|V0|K1|V1], sQ overlaps K1

    const int tid = threadIdx.x, lane = tid & 31, w = tid >> 5;
    const int tg = lane & 3, gr = lane >> 2;
    const int qt = blockIdx.x, h = blockIdx.y, b = blockIdx.z;

    const __nv_bfloat16* Qp = g_Qh + (size_t)(b * kS + qt * 128) * kDM + h * kDH;
    const __nv_bfloat16* Kp = g_Kh + (size_t)(b * kS) * kDM + h * kDH;
    const __nv_bfloat16* Vp = g_Vh + (size_t)(b * kS) * kDM + h * kDH;

    const uint32_t smaddr = (uint32_t)__cvta_generic_to_shared(sm);
    uint32_t* const sQ = sm + 9216;
    const uint32_t kbB[2] = { smaddr,            smaddr + 9216 * 4 };
    const uint32_t vbB[2] = { smaddr + 4608 * 4, smaddr + 13824 * 4 };
    constexpr uint32_t HALFB = 64 * ST * 4;

    const uint32_t ONES = 0x3F803F80u;

    // Fill Q tile (plain copy — ce folded into Wq)
    {
        const int r = tid >> 1, hf = tid & 1;
        const uint4* src = (const uint4*)(Qp + (size_t)r * kDM + hf * 32);
        uint4* dst = (uint4*)(sQ + r * ST + hf * 16);
        dst[0] = src[0]; dst[1] = src[1]; dst[2] = src[2]; dst[3] = src[3];
    }
    __syncthreads();

    // Q fragment preload
    const int q_row = w * 16 + ((lane >> 3) & 1) * 8 + (lane & 7);
    const int q_wrd = (lane >> 4) * 4;
    uint32_t qf[4][4];
#pragma unroll
    for (int ks = 0; ks < 4; ks++)
        ldsm4(qf[ks], smaddr + 9216 * 4 + (q_row * ST + ks * 8 + q_wrd) * 4);

    // cp.async K/V: rows rk+{0,32,64,96}; chunk qk (8 bf16 each)
    const int rk = tid >> 3, qk = tid & 7;
    const __nv_bfloat16* gK = Kp + (size_t)rk * kDM + qk * 8;
    const __nv_bfloat16* gV = Vp + (size_t)rk * kDM + qk * 8;
    auto ISSUEKV = [&](int kt, int buf) {
        const uint32_t kb = kbB[buf], vb = vbB[buf];
        const __nv_bfloat16* pk = gK + (size_t)kt * 128 * kDM;
        const __nv_bfloat16* pv = gV + (size_t)kt * 128 * kDM;
#pragma unroll
        for (int j = 0; j < 4; j++) {
            cpasync16(kb + ((rk + 32 * j) * ST + qk * 4) * 4, pk + (size_t)(32 * j) * kDM);
            cpasync16(vb + ((rk + 32 * j) * ST + qk * 4) * 4, pv + (size_t)(32 * j) * kDM);
        }
    };

    ISSUEKV(0, 0); CP_COMMIT();

    const int bf_row = ((lane >> 4) & 1) * 8 + (lane & 7);
    const int bf_wrd = ((lane >> 3) & 1) * 4;
    const int tv_row = ((lane >> 3) & 1) * 8 + (lane & 7);
    const int tv_wrd = ((lane >> 4) & 1) * 4;

    float accO[8][4];
#pragma unroll
    for (int nf = 0; nf < 8; nf++)
#pragma unroll
        for (int j = 0; j < 4; j++) accO[nf][j] = 0.f;
    float lacc[4] = {0.f, 0.f, 0.f, 0.f};

    for (int kt = 0; kt < kS / 128; kt++) {
        const int buf = kt & 1;
        CP_WAIT0();
        __syncthreads();
        if (kt + 1 < kS / 128) { ISSUEKV(kt + 1, buf ^ 1); CP_COMMIT(); }

#pragma unroll
        for (int half = 0; half < 2; half++) {
            const uint32_t kbase = kbB[buf] + half * HALFB;
            const uint32_t vbase = vbB[buf] + half * HALFB;

            float sacc[8][4];
#pragma unroll
            for (int nf = 0; nf < 8; nf++)
#pragma unroll
                for (int j = 0; j < 4; j++) sacc[nf][j] = 0.f;
#pragma unroll
            for (int ks = 0; ks < 4; ks++)
#pragma unroll
                for (int p = 0; p < 4; p++) {
                    uint32_t bq[4];
                    ldsm4(bq, kbase + ((p * 16 + bf_row) * ST + ks * 8 + bf_wrd) * 4);
                    mma16816(sacc[2 * p],     qf[ks], bq[0], bq[1]);
                    mma16816(sacc[2 * p + 1], qf[ks], bq[2], bq[3]);
                }

            uint32_t pf[4][4];
#pragma unroll
            for (int ks = 0; ks < 4; ks++) {
                pf[ks][0] = ex2bf2(packbf(sacc[2 * ks][0],     sacc[2 * ks][1]));
                pf[ks][1] = ex2bf2(packbf(sacc[2 * ks][2],     sacc[2 * ks][3]));
                pf[ks][2] = ex2bf2(packbf(sacc[2 * ks + 1][0], sacc[2 * ks + 1][1]));
                pf[ks][3] = ex2bf2(packbf(sacc[2 * ks + 1][2], sacc[2 * ks + 1][3]));
            }

#pragma unroll
            for (int ks = 0; ks < 4; ks++)
                mma16816(lacc, pf[ks], ONES, ONES);

#pragma unroll
            for (int ks = 0; ks < 4; ks++)
#pragma unroll
                for (int p = 0; p < 4; p++) {
                    uint32_t bq[4];
                    ldsm4t(bq, vbase + ((ks * 16 + tv_row) * ST + p * 8 + tv_wrd) * 4);
                    mma16816(accO[2 * p],     pf[ks], bq[0], bq[1]);
                    mma16816(accO[2 * p + 1], pf[ks], bq[2], bq[3]);
                }
        }
    }

    const float il0 = 1.f / lacc[0], il1 = 1.f / lacc[2];
    const int grow = b * kS + qt * 128 + w * 16 + gr;
    uint32_t* Co = (uint32_t*)g_AO;
#pragma unroll
    for (int nf = 0; nf < 8; nf++) {
        const size_t cw = (size_t)grow * 512 + h * 32 + nf * 4 + tg;
        Co[cw]            = packbf(accO[nf][0] * il0, accO[nf][1] * il0);
        Co[cw + 8 * 512]  = packbf(accO[nf][2] * il1, accO[nf][3] * il1);
    }
}

// ---------------------------------------------------------------------------
// Row LayerNorm over g_X
// ---------------------------------------------------------------------------
__global__ __launch_bounds__(256) void ln_kernel(
    const float* __restrict__ gamma, const float* __restrict__ beta,
    float* __restrict__ out)
{
    __shared__ float red[8];
    const int row = blockIdx.x;
    const int tid = threadIdx.x;
    const float* x = g_X + (size_t)row * kDM;

    float4 v = *(const float4*)(x + tid * 4);
    float s = v.x + v.y + v.z + v.w;
#pragma unroll
    for (int o = 16; o; o >>= 1) s += __shfl_xor_sync(0xffffffffu, s, o);
    if ((tid & 31) == 0) red[tid >> 5] = s;
    __syncthreads();
    float tot = red[0] + red[1] + red[2] + red[3] + red[4] + red[5] + red[6] + red[7];
    float mu = tot * (1.f / kDM);

    float d0 = v.x - mu, d1 = v.y - mu, d2 = v.z - mu, d3 = v.w - mu;
    float ss = d0 * d0 + d1 * d1 + d2 * d2 + d3 * d3;
#pragma unroll
    for (int o = 16; o; o >>= 1) ss += __shfl_xor_sync(0xffffffffu, ss, o);
    __syncthreads();
    if ((tid & 31) == 0) red[tid >> 5] = ss;
    __syncthreads();
    float vtot = red[0] + red[1] + red[2] + red[3] + red[4] + red[5] + red[6] + red[7];
    float rstd = rsqrtf(vtot * (1.f / kDM) + 1e-6f);

    int c = tid * 4;
    float4 o4;
    o4.x = d0 * rstd * gamma[c + 0] + beta[c + 0];
    o4.y = d1 * rstd * gamma[c + 1] + beta[c + 1];
    o4.z = d2 * rstd * gamma[c + 2] + beta[c + 2];
    o4.w = d3 * rstd * gamma[c + 3] + beta[c + 3];
    *(float4*)(out + (size_t)row * kDM + c) = o4;
}

// ---------------------------------------------------------------------------
extern "C" void kernel_launch(void* const* d_in, const int* in_sizes, int n_in,
                              void* d_out, int out_size)
{
    const float* q     = (const float*)d_in[0];
    const float* k     = (const float*)d_in[1];
    const float* v     = (const float*)d_in[2];
    const float* Wq    = (const float*)d_in[3];
    const float* Wk    = (const float*)d_in[4];
    const float* Wv    = (const float*)d_in[5];
    const float* Wfc   = (const float*)d_in[6];
    const float* bfc   = (const float*)d_in[7];
    const float* gamma = (const float*)d_in[8];
    const float* beta  = (const float*)d_in[9];
    float* out = (float*)d_out;

    prep_kernel<<<dim3(64, 64, 7), dim3(32, 8)>>>(q, k, v, Wq, Wk, Wv, Wfc);
    gemm_qkv_kernel<<<dim3(8, 32, 3), 128>>>();
    attn_kernel<<<dim3(16, 16, 2), 256>>>();
    gemm_out_kernel<<<dim3(8, 32, 1), 128>>>(bfc, q);
    ln_kernel<<<kM, 256>>>(gamma, beta, out);
}

// round 17
// speedup vs baseline: 1.1764x; 1.1764x over previous
#include <cuda_runtime.h>
#include <cuda_bf16.h>
#include <cstdint>
#include <cstddef>

#define kB  2
#define kS  2048
#define kDM 1024
#define kNH 16
#define kDH 64
#define kM  (kB * kS)

// Scratch (static device globals; no allocation allowed)
__device__ __nv_bfloat16 g_Wt[4][kDM * kDM];   // bf16 weights transposed [n][k]
__device__ __nv_bfloat16 g_Ab[3][kM * kDM];    // bf16 copies of q,k,v
__device__ __nv_bfloat16 g_Qh[kM * kDM];       // pre-scaled by ce (Wq folded)
__device__ __nv_bfloat16 g_Kh[kM * kDM];
__device__ __nv_bfloat16 g_Vh[kM * kDM];
__device__ __nv_bfloat16 g_AO[kM * kDM];
__device__ float         g_X [kM * kDM];

// ---------------------------------------------------------------------------
__device__ __forceinline__ uint32_t packbf(float lo, float hi) {
    uint32_t r;
    asm("cvt.rn.bf16x2.f32 %0, %1, %2;" : "=r"(r) : "f"(hi), "f"(lo));
    return r;
}
__device__ __forceinline__ uint32_t ex2bf2(uint32_t x) {
    uint32_t r;
    asm("ex2.approx.ftz.bf16x2 %0, %1;" : "=r"(r) : "r"(x));
    return r;
}
__device__ __forceinline__ void mma16816(float c[4], const uint32_t a[4], uint32_t b0, uint32_t b1) {
    asm volatile(
        "mma.sync.aligned.m16n8k16.row.col.f32.bf16.bf16.f32 "
        "{%0,%1,%2,%3}, {%4,%5,%6,%7}, {%8,%9}, {%0,%1,%2,%3};"
        : "+f"(c[0]), "+f"(c[1]), "+f"(c[2]), "+f"(c[3])
        : "r"(a[0]), "r"(a[1]), "r"(a[2]), "r"(a[3]), "r"(b0), "r"(b1));
}
__device__ __forceinline__ void ldsm4(uint32_t r[4], uint32_t addr) {
    asm volatile("ldmatrix.sync.aligned.m8n8.x4.shared.b16 {%0,%1,%2,%3}, [%4];"
                 : "=r"(r[0]), "=r"(r[1]), "=r"(r[2]), "=r"(r[3]) : "r"(addr));
}
__device__ __forceinline__ void ldsm4t(uint32_t r[4], uint32_t addr) {
    asm volatile("ldmatrix.sync.aligned.m8n8.x4.trans.shared.b16 {%0,%1,%2,%3}, [%4];"
                 : "=r"(r[0]), "=r"(r[1]), "=r"(r[2]), "=r"(r[3]) : "r"(addr));
}
__device__ __forceinline__ void cpasync16(uint32_t dst, const void* src) {
    asm volatile("cp.async.cg.shared.global [%0], [%1], 16;" :: "r"(dst), "l"(src));
}
#define CP_COMMIT()  asm volatile("cp.async.commit_group;" ::: "memory")
#define CP_WAIT0()   asm volatile("cp.async.wait_group 0;" ::: "memory")
#define CP_WAIT1()   asm volatile("cp.async.wait_group 1;" ::: "memory")

// ---------------------------------------------------------------------------
// Weight transpose + convert: W[k][n] fp32 -> g_Wt[z][n][k] bf16
// (z==0 folds softmax temperature*log2e into Wq)
// ---------------------------------------------------------------------------
__global__ void wtrans_kernel(const float* __restrict__ Wq, const float* __restrict__ Wk,
                              const float* __restrict__ Wv, const float* __restrict__ Wfc)
{
    __shared__ float tile[32][33];
    const int z = blockIdx.z;
    const float* W = (z == 0) ? Wq : (z == 1) ? Wk : (z == 2) ? Wv : Wfc;
    const float scale = (z == 0) ? 0.125f * 1.4426950408889634f : 1.0f;
    const int n0 = blockIdx.x * 32, k0 = blockIdx.y * 32;
    const int tx = threadIdx.x, ty = threadIdx.y;
#pragma unroll
    for (int j = 0; j < 4; j++)
        tile[ty + 8 * j][tx] = W[(size_t)(k0 + ty + 8 * j) * kDM + n0 + tx];
    __syncthreads();
#pragma unroll
    for (int j = 0; j < 4; j++)
        g_Wt[z][(size_t)(n0 + ty + 8 * j) * kDM + k0 + tx] =
            __float2bfloat16(tile[tx][ty + 8 * j] * scale);
}

// ---------------------------------------------------------------------------
// fp32 -> bf16 convert for q,k,v
// ---------------------------------------------------------------------------
__global__ __launch_bounds__(256) void tobf16_kernel(
    const float* __restrict__ q, const float* __restrict__ k, const float* __restrict__ v)
{
    const int z = blockIdx.z;
    const float* src = (z == 0) ? q : (z == 1) ? k : v;
    const size_t i = (size_t)blockIdx.x * 256 + threadIdx.x;
    float4 x = ((const float4*)src)[i];
    uint2 o;
    o.x = packbf(x.x, x.y);
    o.y = packbf(x.z, x.w);
    ((uint2*)g_Ab[z])[i] = o;
}

// ---------------------------------------------------------------------------
// 128x128 GEMM, bf16 mma m16n8k16, 3-stage cp.async (wait_group 1), k=32.
// (R15 proven version, unchanged)
// ---------------------------------------------------------------------------
template <bool OUTF32>
__device__ __forceinline__ void gemm_body(
    const __nv_bfloat16* __restrict__ A, const __nv_bfloat16* __restrict__ Bt,
    void* Cp, const float* __restrict__ bias, const float* __restrict__ resid,
    int m0, int n0)
{
    constexpr int ST = 20;
    __shared__ uint32_t sA[3][128 * ST];
    __shared__ uint32_t sB[3][128 * ST];

    const int tid = threadIdx.x, lane = tid & 31, wid = tid >> 5;
    const int wm = wid & 3, wn = wid >> 2, tg = lane & 3, gr = lane >> 2;

    const uint32_t aA = (uint32_t)__cvta_generic_to_shared(sA);
    const uint32_t aB = (uint32_t)__cvta_generic_to_shared(sB);

    const int r4 = tid >> 2, q4 = tid & 3;
    const __nv_bfloat16* gA = A + (size_t)(m0 + r4) * kDM + q4 * 8;
    const __nv_bfloat16* gB = Bt + (size_t)(n0 + r4) * kDM + q4 * 8;
    const uint32_t dA0 = aA + (r4 * ST + q4 * 4) * 4;
    const uint32_t dA1 = aA + ((r4 + 64) * ST + q4 * 4) * 4;
    const uint32_t dB0 = aB + (r4 * ST + q4 * 4) * 4;
    const uint32_t dB1 = aB + ((r4 + 64) * ST + q4 * 4) * 4;
    constexpr uint32_t BUFB = 128 * ST * 4;

    auto ISSUE = [&](int kt, int buf) {
        const __nv_bfloat16* pa = gA + kt * 32;
        const __nv_bfloat16* pb = gB + kt * 32;
        const uint32_t bo = buf * BUFB;
        cpasync16(dA0 + bo, pa);
        cpasync16(dA1 + bo, pa + 64 * kDM);
        cpasync16(dB0 + bo, pb);
        cpasync16(dB1 + bo, pb + 64 * kDM);
    };

    const int a_row = wm * 32 + ((lane >> 3) & 1) * 8 + (lane & 7);
    const int a_wrd = (lane >> 4) * 4;
    const int b_row = wn * 64 + ((lane >> 4) & 1) * 8 + (lane & 7);
    const int b_wrd = ((lane >> 3) & 1) * 4;

    float acc[2][8][4];
#pragma unroll
    for (int i = 0; i < 2; i++)
#pragma unroll
        for (int j = 0; j < 8; j++)
#pragma unroll
            for (int l = 0; l < 4; l++) acc[i][j][l] = 0.f;

    ISSUE(0, 0); CP_COMMIT();
    ISSUE(1, 1); CP_COMMIT();

    int cur = 0;
    for (int kt = 0; kt < 32; kt++) {
        if (kt == 31) { CP_WAIT0(); } else { CP_WAIT1(); }
        __syncthreads();
        if (kt + 2 < 32) {
            int nx = cur + 2; if (nx >= 3) nx -= 3;
            ISSUE(kt + 2, nx); CP_COMMIT();
        }

        const uint32_t sAb = aA + cur * BUFB;
        const uint32_t sBb = aB + cur * BUFB;
#pragma unroll
        for (int ks = 0; ks < 2; ks++) {
            uint32_t af[2][4];
            ldsm4(af[0], sAb + ((a_row)      * ST + ks * 8 + a_wrd) * 4);
            ldsm4(af[1], sAb + ((a_row + 16) * ST + ks * 8 + a_wrd) * 4);
#pragma unroll
            for (int p = 0; p < 4; p++) {
                uint32_t bq[4];
                ldsm4(bq, sBb + ((b_row + p * 16) * ST + ks * 8 + b_wrd) * 4);
                mma16816(acc[0][2 * p],     af[0], bq[0], bq[1]);
                mma16816(acc[0][2 * p + 1], af[0], bq[2], bq[3]);
                mma16816(acc[1][2 * p],     af[1], bq[0], bq[1]);
                mma16816(acc[1][2 * p + 1], af[1], bq[2], bq[3]);
            }
        }
        cur = (cur + 1 == 3) ? 0 : cur + 1;
    }

    if (OUTF32) {
        float* C = (float*)Cp;
#pragma unroll
        for (int mf = 0; mf < 2; mf++)
#pragma unroll
            for (int nf = 0; nf < 8; nf++) {
                const int col = n0 + wn * 64 + nf * 8 + tg * 2;
#pragma unroll
                for (int rr = 0; rr < 2; rr++) {
                    const int r = m0 + wm * 32 + mf * 16 + gr + rr * 8;
                    float2 v;
                    v.x = acc[mf][nf][rr * 2 + 0] + bias[col]     + resid[(size_t)r * kDM + col];
                    v.y = acc[mf][nf][rr * 2 + 1] + bias[col + 1] + resid[(size_t)r * kDM + col + 1];
                    *(float2*)(C + (size_t)r * kDM + col) = v;
                }
            }
    } else {
        uint32_t* C = (uint32_t*)Cp;
        const int colw = (n0 >> 1) + wn * 32;
#pragma unroll
        for (int mf = 0; mf < 2; mf++)
#pragma unroll
            for (int nf = 0; nf < 8; nf++) {
#pragma unroll
                for (int rr = 0; rr < 2; rr++) {
                    const int r = m0 + wm * 32 + mf * 16 + gr + rr * 8;
                    C[(size_t)r * 512 + colw + nf * 4 + tg] =
                        packbf(acc[mf][nf][rr * 2 + 0], acc[mf][nf][rr * 2 + 1]);
                }
            }
    }
}

__global__ __launch_bounds__(256, 2) void gemm_qkv_kernel() {
    const int z = blockIdx.z;
    __nv_bfloat16* C = (z == 0) ? g_Qh : (z == 1) ? g_Kh : g_Vh;
    gemm_body<false>(g_Ab[z], g_Wt[z], C, nullptr, nullptr, blockIdx.y * 128, blockIdx.x * 128);
}

__global__ __launch_bounds__(256, 2) void gemm_out_kernel(
    const float* __restrict__ bfc, const float* __restrict__ resid)
{
    gemm_body<true>(g_AO, g_Wt[3], g_X, bfc, resid, blockIdx.y * 128, blockIdx.x * 128);
}

// ---------------------------------------------------------------------------
// Flash attention: 1 CTA per (b, h, 128-row Q tile), 128 thr = 4 warps,
// 32 Q rows per warp (each K/V ldsm feeds 4 MMAs -> smem traffic halved).
// Keys processed in 32-wide chunks (S->exp->PV per chunk) to cap registers.
// 128-key K/V smem tiles double-buffered; Q pre-scaled; packed bf16x2 exp;
// row sums via ones-column MMA; V via ldmatrix.trans.
// ---------------------------------------------------------------------------
__global__ __launch_bounds__(128, 2) void attn_kernel() {
    constexpr int ST = 36;
    __shared__ uint32_t sm[18432];  // [K0|V0|K1|V1], sQ overlaps K1

    const int tid = threadIdx.x, lane = tid & 31, w = tid >> 5;
    const int tg = lane & 3, gr = lane >> 2;
    const int qt = blockIdx.x, h = blockIdx.y, b = blockIdx.z;

    const __nv_bfloat16* Qp = g_Qh + (size_t)(b * kS + qt * 128) * kDM + h * kDH;
    const __nv_bfloat16* Kp = g_Kh + (size_t)(b * kS) * kDM + h * kDH;
    const __nv_bfloat16* Vp = g_Vh + (size_t)(b * kS) * kDM + h * kDH;

    const uint32_t smaddr = (uint32_t)__cvta_generic_to_shared(sm);
    uint32_t* const sQ = sm + 9216;  // overlaps K1
    const uint32_t kbB[2] = { smaddr,            smaddr + 9216 * 4 };
    const uint32_t vbB[2] = { smaddr + 4608 * 4, smaddr + 13824 * 4 };

    const uint32_t ONES = 0x3F803F80u;

    // Fill Q tile: one row (32 words) per thread
    {
        const uint4* src = (const uint4*)(Qp + (size_t)tid * kDM);
        uint4* dst = (uint4*)(sQ + tid * ST);
#pragma unroll
        for (int j = 0; j < 8; j++) dst[j] = src[j];
    }
    __syncthreads();

    // Q fragment preload: 32 rows per warp (mf = 0,1)
    const int q_row = w * 32 + ((lane >> 3) & 1) * 8 + (lane & 7);
    const int q_wrd = (lane >> 4) * 4;
    uint32_t qf[2][4][4];
#pragma unroll
    for (int mf = 0; mf < 2; mf++)
#pragma unroll
        for (int ks = 0; ks < 4; ks++)
            ldsm4(qf[mf][ks], smaddr + 9216 * 4 + ((q_row + mf * 16) * ST + ks * 8 + q_wrd) * 4);

    // cp.async K/V: 128 threads cover 128 rows x 8 chunks: rows rk+{0,16,..112}
    const int rk = tid >> 3, qk = tid & 7;
    const __nv_bfloat16* gK = Kp + (size_t)rk * kDM + qk * 8;
    const __nv_bfloat16* gV = Vp + (size_t)rk * kDM + qk * 8;
    auto ISSUEKV = [&](int kt, int buf) {
        const uint32_t kb = kbB[buf], vb = vbB[buf];
        const __nv_bfloat16* pk = gK + (size_t)kt * 128 * kDM;
        const __nv_bfloat16* pv = gV + (size_t)kt * 128 * kDM;
#pragma unroll
        for (int j = 0; j < 8; j++) {
            cpasync16(kb + ((rk + 16 * j) * ST + qk * 4) * 4, pk + (size_t)(16 * j) * kDM);
            cpasync16(vb + ((rk + 16 * j) * ST + qk * 4) * 4, pv + (size_t)(16 * j) * kDM);
        }
    };

    ISSUEKV(0, 0); CP_COMMIT();

    const int bf_row = ((lane >> 4) & 1) * 8 + (lane & 7);
    const int bf_wrd = ((lane >> 3) & 1) * 4;
    const int tv_row = ((lane >> 3) & 1) * 8 + (lane & 7);
    const int tv_wrd = ((lane >> 4) & 1) * 4;

    float accO[2][8][4];
#pragma unroll
    for (int mf = 0; mf < 2; mf++)
#pragma unroll
        for (int nf = 0; nf < 8; nf++)
#pragma unroll
            for (int j = 0; j < 4; j++) accO[mf][nf][j] = 0.f;
    float lacc[2][4] = {{0.f, 0.f, 0.f, 0.f}, {0.f, 0.f, 0.f, 0.f}};

    for (int kt = 0; kt < kS / 128; kt++) {
        const int buf = kt & 1;
        CP_WAIT0();
        __syncthreads();
        if (kt + 1 < kS / 128) { ISSUEKV(kt + 1, buf ^ 1); CP_COMMIT(); }

#pragma unroll
        for (int kc = 0; kc < 4; kc++) {  // 32-key chunks
            const uint32_t kbase = kbB[buf] + (kc * 32) * ST * 4;
            const uint32_t vbase = vbB[buf] + (kc * 32) * ST * 4;

            // S chunk = Q K^T (32 keys)
            float sacc[2][4][4];
#pragma unroll
            for (int mf = 0; mf < 2; mf++)
#pragma unroll
                for (int nf = 0; nf < 4; nf++)
#pragma unroll
                    for (int j = 0; j < 4; j++) sacc[mf][nf][j] = 0.f;
#pragma unroll
            for (int ks = 0; ks < 4; ks++)
#pragma unroll
                for (int p = 0; p < 2; p++) {
                    uint32_t bq[4];
                    ldsm4(bq, kbase + ((p * 16 + bf_row) * ST + ks * 8 + bf_wrd) * 4);
                    mma16816(sacc[0][2 * p],     qf[0][ks], bq[0], bq[1]);
                    mma16816(sacc[0][2 * p + 1], qf[0][ks], bq[2], bq[3]);
                    mma16816(sacc[1][2 * p],     qf[1][ks], bq[0], bq[1]);
                    mma16816(sacc[1][2 * p + 1], qf[1][ks], bq[2], bq[3]);
                }

            // exp2 in packed bf16x2 domain -> P A-fragments
            uint32_t pf[2][2][4];
#pragma unroll
            for (int mf = 0; mf < 2; mf++)
#pragma unroll
                for (int k2 = 0; k2 < 2; k2++) {
                    pf[mf][k2][0] = ex2bf2(packbf(sacc[mf][2 * k2][0],     sacc[mf][2 * k2][1]));
                    pf[mf][k2][1] = ex2bf2(packbf(sacc[mf][2 * k2][2],     sacc[mf][2 * k2][3]));
                    pf[mf][k2][2] = ex2bf2(packbf(sacc[mf][2 * k2 + 1][0], sacc[mf][2 * k2 + 1][1]));
                    pf[mf][k2][3] = ex2bf2(packbf(sacc[mf][2 * k2 + 1][2], sacc[mf][2 * k2 + 1][3]));
                }

            // Row sums: lacc += P @ ones
#pragma unroll
            for (int k2 = 0; k2 < 2; k2++) {
                mma16816(lacc[0], pf[0][k2], ONES, ONES);
                mma16816(lacc[1], pf[1][k2], ONES, ONES);
            }

            // O += P V (V [s][d] in smem, trans frags)
#pragma unroll
            for (int k2 = 0; k2 < 2; k2++)
#pragma unroll
                for (int p = 0; p < 4; p++) {
                    uint32_t bq[4];
                    ldsm4t(bq, vbase + ((k2 * 16 + tv_row) * ST + p * 8 + tv_wrd) * 4);
                    mma16816(accO[0][2 * p],     pf[0][k2], bq[0], bq[1]);
                    mma16816(accO[0][2 * p + 1], pf[0][k2], bq[2], bq[3]);
                    mma16816(accO[1][2 * p],     pf[1][k2], bq[0], bq[1]);
                    mma16816(accO[1][2 * p + 1], pf[1][k2], bq[2], bq[3]);
                }
        }
    }

    // Epilogue
    uint32_t* Co = (uint32_t*)g_AO;
#pragma unroll
    for (int mf = 0; mf < 2; mf++) {
        const float il0 = 1.f / lacc[mf][0], il1 = 1.f / lacc[mf][2];
        const int grow = b * kS + qt * 128 + w * 32 + mf * 16 + gr;
#pragma unroll
        for (int nf = 0; nf < 8; nf++) {
            const size_t cw = (size_t)grow * 512 + h * 32 + nf * 4 + tg;
            Co[cw]           = packbf(accO[mf][nf][0] * il0, accO[mf][nf][1] * il0);
            Co[cw + 8 * 512] = packbf(accO[mf][nf][2] * il1, accO[mf][nf][3] * il1);
        }
    }
}

// ---------------------------------------------------------------------------
// Row LayerNorm over g_X
// ---------------------------------------------------------------------------
__global__ __launch_bounds__(256) void ln_kernel(
    const float* __restrict__ gamma, const float* __restrict__ beta,
    float* __restrict__ out)
{
    __shared__ float red[8];
    const int row = blockIdx.x;
    const int tid = threadIdx.x;
    const float* x = g_X + (size_t)row * kDM;

    float4 v = *(const float4*)(x + tid * 4);
    float s = v.x + v.y + v.z + v.w;
#pragma unroll
    for (int o = 16; o; o >>= 1) s += __shfl_xor_sync(0xffffffffu, s, o);
    if ((tid & 31) == 0) red[tid >> 5] = s;
    __syncthreads();
    float tot = red[0] + red[1] + red[2] + red[3] + red[4] + red[5] + red[6] + red[7];
    float mu = tot * (1.f / kDM);

    float d0 = v.x - mu, d1 = v.y - mu, d2 = v.z - mu, d3 = v.w - mu;
    float ss = d0 * d0 + d1 * d1 + d2 * d2 + d3 * d3;
#pragma unroll
    for (int o = 16; o; o >>= 1) ss += __shfl_xor_sync(0xffffffffu, ss, o);
    __syncthreads();
    if ((tid & 31) == 0) red[tid >> 5] = ss;
    __syncthreads();
    float vtot = red[0] + red[1] + red[2] + red[3] + red[4] + red[5] + red[6] + red[7];
    float rstd = rsqrtf(vtot * (1.f / kDM) + 1e-6f);

    int c = tid * 4;
    float4 o4;
    o4.x = d0 * rstd * gamma[c + 0] + beta[c + 0];
    o4.y = d1 * rstd * gamma[c + 1] + beta[c + 1];
    o4.z = d2 * rstd * gamma[c + 2] + beta[c + 2];
    o4.w = d3 * rstd * gamma[c + 3] + beta[c + 3];
    *(float4*)(out + (size_t)row * kDM + c) = o4;
}

// ---------------------------------------------------------------------------
extern "C" void kernel_launch(void* const* d_in, const int* in_sizes, int n_in,
                              void* d_out, int out_size)
{
    const float* q     = (const float*)d_in[0];
    const float* k     = (const float*)d_in[1];
    const float* v     = (const float*)d_in[2];
    const float* Wq    = (const float*)d_in[3];
    const float* Wk    = (const float*)d_in[4];
    const float* Wv    = (const float*)d_in[5];
    const float* Wfc   = (const float*)d_in[6];
    const float* bfc   = (const float*)d_in[7];
    const float* gamma = (const float*)d_in[8];
    const float* beta  = (const float*)d_in[9];
    float* out = (float*)d_out;

    wtrans_kernel<<<dim3(32, 32, 4), dim3(32, 8)>>>(Wq, Wk, Wv, Wfc);
    tobf16_kernel<<<dim3(kM * kDM / 4 / 256, 1, 3), 256>>>(q, k, v);
    gemm_qkv_kernel<<<dim3(8, 32, 3), 256>>>();
    attn_kernel<<<dim3(16, 16, 2), 128>>>();
    gemm_out_kernel<<<dim3(8, 32, 1), 256>>>(bfc, q);
    ln_kernel<<<kM, 256>>>(gamma, beta, out);
}